// round 3
// baseline (speedup 1.0000x reference)
#include <cuda_runtime.h>
#include <math.h>

#define BATCH   32
#define W_GRID  640
#define H_GRID  480
#define IMG_H   480
#define IMG_W   640
#define NPIX    (BATCH * W_GRID * H_GRID)   // 9,830,400
#define NGROUP  (NPIX / 4)                  // 2,457,600 4-pixel groups
#define P1_BLOCKS (148 * 4)                 // fixed pass-1 grid (592)

// per-block maxima from pass 1 (plain stores, overwritten every replay -> no reset kernel)
__device__ float g_blockmax[P1_BLOCKS];

__device__ __forceinline__ float frcp_approx(float x) {
    float r;
    asm("rcp.approx.f32 %0, %1;" : "=f"(r) : "f"(x));
    return r;
}

// 3x3 inverse via adjugate, IEEE divides (runs once per block, negligible cost)
__device__ __forceinline__ void inv3x3(const float* __restrict__ K, float* Ki) {
    float a = K[0], b = K[1], c = K[2];
    float d = K[3], e = K[4], f = K[5];
    float g = K[6], h = K[7], i = K[8];
    float A  =  (e * i - f * h);
    float Bc = -(d * i - f * g);
    float C  =  (d * h - e * g);
    float det = a * A + b * Bc + c * C;
    Ki[0] = __fdiv_rn(A, det);
    Ki[1] = __fdiv_rn(-(b * i - c * h), det);
    Ki[2] = __fdiv_rn((b * f - c * e), det);
    Ki[3] = __fdiv_rn(Bc, det);
    Ki[4] = __fdiv_rn((a * i - c * g), det);
    Ki[5] = __fdiv_rn(-(a * f - c * d), det);
    Ki[6] = __fdiv_rn(C, det);
    Ki[7] = __fdiv_rn(-(a * h - b * g), det);
    Ki[8] = __fdiv_rn((a * e - b * d), det);
}

// projective chain up to (q0, q1, rden) — one approx reciprocal, no divides
__device__ __forceinline__ void compute_q(
    float u, float v, float dpt,
    const float* __restrict__ Tb,
    const float* Ki, const float* Kr,
    float& q0, float& q1, float& rden)
{
    float a0 = fmaf(u, Ki[0], fmaf(v, Ki[3], Ki[6]));
    float a1 = fmaf(u, Ki[1], fmaf(v, Ki[4], Ki[7]));
    float a2 = fmaf(u, Ki[2], fmaf(v, Ki[5], Ki[8]));

    float p0 = dpt * a0;
    float p1 = dpt * a1;
    float p2 = dpt * a2;

    float t0 = fmaf(p0, Tb[0], fmaf(p1, Tb[4], fmaf(p2, Tb[8],  Tb[12])));
    float t1 = fmaf(p0, Tb[1], fmaf(p1, Tb[5], fmaf(p2, Tb[9],  Tb[13])));
    float t2 = fmaf(p0, Tb[2], fmaf(p1, Tb[6], fmaf(p2, Tb[10], Tb[14])));

    q0 = fmaf(t0, Kr[0], fmaf(t1, Kr[3], t2 * Kr[6]));
    q1 = fmaf(t0, Kr[1], fmaf(t1, Kr[4], t2 * Kr[7]));
    float q2 = fmaf(t0, Kr[2], fmaf(t1, Kr[5], t2 * Kr[8]));

    rden = frcp_approx(q2 + 1e-4f);
}

// Pass 1: per-block max of uv over all pixels (4 px / iteration), plain store.
__global__ void uv_max_kernel(
    const float* __restrict__ depth,
    const float* __restrict__ T,
    const float* __restrict__ K)
{
    __shared__ float sKi[9];
    if (threadIdx.x == 0) inv3x3(K, sKi);
    __syncthreads();

    float Ki[9], Kr[9];
    #pragma unroll
    for (int i = 0; i < 9; i++) { Ki[i] = sKi[i]; Kr[i] = K[i]; }

    float local_max = -INFINITY;
    int stride = gridDim.x * blockDim.x;
    for (int g = blockIdx.x * blockDim.x + threadIdx.x; g < NGROUP; g += stride) {
        int hj4 = (g % (H_GRID / 4)) * 4;
        int t   = g / (H_GRID / 4);
        int wi  = t % W_GRID;
        int b   = t / W_GRID;

        float4 d4 = *reinterpret_cast<const float4*>(
            depth + ((size_t)b * W_GRID + wi) * H_GRID + hj4);
        const float* Tb = T + b * 16;
        float v = (float)wi;

        float dv[4] = {d4.x, d4.y, d4.z, d4.w};
        #pragma unroll
        for (int k = 0; k < 4; k++) {
            float q0, q1, rden;
            compute_q((float)(hj4 + k), v, dv[k], Tb, Ki, Kr, q0, q1, rden);
            local_max = fmaxf(local_max, fmaxf(q0 * rden, q1 * rden));
        }
    }

    // warp reduction then block reduction
    #pragma unroll
    for (int off = 16; off > 0; off >>= 1)
        local_max = fmaxf(local_max, __shfl_xor_sync(0xffffffffu, local_max, off));

    __shared__ float smax[8];
    int warp = threadIdx.x >> 5;
    int lane = threadIdx.x & 31;
    if (lane == 0) smax[warp] = local_max;
    __syncthreads();
    if (warp == 0) {
        float m = (lane < (blockDim.x >> 5)) ? smax[lane] : -INFINITY;
        #pragma unroll
        for (int off = 4; off > 0; off >>= 1)
            m = fmaxf(m, __shfl_xor_sync(0xffffffffu, m, off));
        if (lane == 0) g_blockmax[blockIdx.x] = m;
    }
}

// Pass 2: reduce block maxima, recompute uv, normalize, bilinear sample.
__global__ void sample_kernel(
    const float* __restrict__ depth,
    const float* __restrict__ T,
    const float* __restrict__ K,
    const float* __restrict__ image,
    float* __restrict__ out)
{
    // --- reduce the 592 per-block maxima (L2-resident) + compute Ki, in parallel ---
    __shared__ float sKi[9];
    __shared__ float swarp[8];
    __shared__ float s_gmax;
    if (threadIdx.x == 0) inv3x3(K, sKi);

    {
        float m = -INFINITY;
        for (int i = threadIdx.x; i < P1_BLOCKS; i += blockDim.x)
            m = fmaxf(m, g_blockmax[i]);
        #pragma unroll
        for (int off = 16; off > 0; off >>= 1)
            m = fmaxf(m, __shfl_xor_sync(0xffffffffu, m, off));
        int warp = threadIdx.x >> 5;
        int lane = threadIdx.x & 31;
        if (lane == 0) swarp[warp] = m;
        __syncthreads();
        if (warp == 0) {
            float mm = (lane < 8) ? swarp[lane] : -INFINITY;
            #pragma unroll
            for (int off = 4; off > 0; off >>= 1)
                mm = fmaxf(mm, __shfl_xor_sync(0xffffffffu, mm, off));
            if (lane == 0) s_gmax = mm;
        }
        __syncthreads();
    }

    int g = blockIdx.x * blockDim.x + threadIdx.x;
    if (g >= NGROUP) return;

    int hj4 = (g % (H_GRID / 4)) * 4;
    int t   = g / (H_GRID / 4);
    int wi  = t % W_GRID;
    int b   = t / W_GRID;

    float Ki[9], Kr[9];
    #pragma unroll
    for (int i = 0; i < 9; i++) { Ki[i] = sKi[i]; Kr[i] = K[i]; }

    float gmax = s_gmax;
    // x = uv0 * (W/gmax) - 0.5 ; y = uv1 * (H/gmax) - 0.5   (folded normalize)
    float rg = __fdiv_rn(1.0f, gmax);
    float sx = (float)IMG_W * rg;
    float sy = (float)IMG_H * rg;

    float4 d4 = *reinterpret_cast<const float4*>(
        depth + ((size_t)b * W_GRID + wi) * H_GRID + hj4);
    const float* Tb = T + b * 16;
    float v = (float)wi;

    const float* img_b = image + (size_t)b * 3 * IMG_H * IMG_W;

    float r[3][4];
    float dv[4] = {d4.x, d4.y, d4.z, d4.w};

    #pragma unroll
    for (int k = 0; k < 4; k++) {
        float q0, q1, rden;
        compute_q((float)(hj4 + k), v, dv[k], Tb, Ki, Kr, q0, q1, rden);

        float x = fmaf(q0 * rden, sx, -0.5f);
        float y = fmaf(q1 * rden, sy, -0.5f);

        float x0f = floorf(x);
        float y0f = floorf(y);
        float wx = x - x0f;
        float wy = y - y0f;
        float x1f = x0f + 1.0f;
        float y1f = y0f + 1.0f;

        float vx0 = (x0f >= 0.0f && x0f <= (float)(IMG_W - 1)) ? 1.0f : 0.0f;
        float vx1 = (x1f >= 0.0f && x1f <= (float)(IMG_W - 1)) ? 1.0f : 0.0f;
        float vy0 = (y0f >= 0.0f && y0f <= (float)(IMG_H - 1)) ? 1.0f : 0.0f;
        float vy1 = (y1f >= 0.0f && y1f <= (float)(IMG_H - 1)) ? 1.0f : 0.0f;

        int xi0 = (int)fminf(fmaxf(x0f, 0.0f), (float)(IMG_W - 1));
        int xi1 = (int)fminf(fmaxf(x1f, 0.0f), (float)(IMG_W - 1));
        int yi0 = (int)fminf(fmaxf(y0f, 0.0f), (float)(IMG_H - 1));
        int yi1 = (int)fminf(fmaxf(y1f, 0.0f), (float)(IMG_H - 1));

        float w00 = (1.0f - wx) * (1.0f - wy) * (vx0 * vy0);
        float w01 = wx * (1.0f - wy)          * (vx1 * vy0);
        float w10 = (1.0f - wx) * wy          * (vx0 * vy1);
        float w11 = wx * wy                   * (vx1 * vy1);

        int i00 = yi0 * IMG_W + xi0;
        int i01 = yi0 * IMG_W + xi1;
        int i10 = yi1 * IMG_W + xi0;
        int i11 = yi1 * IMG_W + xi1;

        #pragma unroll
        for (int c = 0; c < 3; c++) {
            const float* ch = img_b + (size_t)c * (IMG_H * IMG_W);
            r[c][k] = w00 * ch[i00] + w01 * ch[i01] + w10 * ch[i10] + w11 * ch[i11];
        }
    }

    size_t out_base = ((size_t)b * 3) * (size_t)(W_GRID * H_GRID)
                    + (size_t)wi * H_GRID + hj4;
    #pragma unroll
    for (int c = 0; c < 3; c++) {
        float4 o = make_float4(r[c][0], r[c][1], r[c][2], r[c][3]);
        *reinterpret_cast<float4*>(out + out_base + (size_t)c * (W_GRID * H_GRID)) = o;
    }
}

extern "C" void kernel_launch(void* const* d_in, const int* in_sizes, int n_in,
                              void* d_out, int out_size) {
    const float* depth = (const float*)d_in[0];   // [32, 640, 480, 1]
    const float* T     = (const float*)d_in[1];   // [32, 4, 4]
    const float* image = (const float*)d_in[2];   // [32, 3, 480, 640]
    const float* K     = (const float*)d_in[3];   // [3, 3]
    float* out = (float*)d_out;                   // [32, 3, 640, 480]

    uv_max_kernel<<<P1_BLOCKS, 256>>>(depth, T, K);
    int blocks = (NGROUP + 255) / 256;            // 9600
    sample_kernel<<<blocks, 256>>>(depth, T, K, image, out);
}

// round 5
// speedup vs baseline: 1.5031x; 1.5031x over previous
#include <cuda_runtime.h>
#include <math.h>

#define BATCH   32
#define W_GRID  640
#define H_GRID  480
#define IMG_H   480
#define IMG_W   640
#define NPIX    (BATCH * W_GRID * H_GRID)   // 9,830,400
#define NGROUP  (NPIX / 4)                  // 2,457,600 4-pixel groups
#define P1_BLOCKS (148 * 4)

// scratch
__device__ unsigned int g_max_bits;
__device__ float g_M[BATCH][12];   // [0..8]=M (row-major), [9..11]=c

__device__ __forceinline__ unsigned int float_to_ordered(float f) {
    unsigned int u = __float_as_uint(f);
    return (u & 0x80000000u) ? ~u : (u | 0x80000000u);
}
__device__ __forceinline__ float ordered_to_float(unsigned int u) {
    unsigned int b = (u & 0x80000000u) ? (u ^ 0x80000000u) : ~u;
    return __uint_as_float(b);
}
__device__ __forceinline__ float frcp_approx(float x) {
    float r;
    asm("rcp.approx.f32 %0, %1;" : "=f"(r) : "f"(x));
    return r;
}

// Setup: reset max; per batch b build M_b = Ki * T33 * K and c_b = T[3,0:3] * K.
__global__ void setup_kernel(const float* __restrict__ T, const float* __restrict__ K) {
    if (threadIdx.x == 0) g_max_bits = 0u;
    int bidx = threadIdx.x;
    if (bidx >= BATCH) return;

    // Ki = inv(K) via adjugate
    float a = K[0], b = K[1], c = K[2];
    float d = K[3], e = K[4], f = K[5];
    float g = K[6], h = K[7], i = K[8];
    float A  =  (e * i - f * h);
    float Bc = -(d * i - f * g);
    float C  =  (d * h - e * g);
    float det = a * A + b * Bc + c * C;
    float Ki[9];
    Ki[0] = __fdiv_rn(A, det);
    Ki[1] = __fdiv_rn(-(b * i - c * h), det);
    Ki[2] = __fdiv_rn((b * f - c * e), det);
    Ki[3] = __fdiv_rn(Bc, det);
    Ki[4] = __fdiv_rn((a * i - c * g), det);
    Ki[5] = __fdiv_rn(-(a * f - c * d), det);
    Ki[6] = __fdiv_rn(C, det);
    Ki[7] = __fdiv_rn(-(a * h - b * g), det);
    Ki[8] = __fdiv_rn((a * e - b * d), det);

    const float* Tb = T + bidx * 16;
    // A2 = T33 * K   (A2[k][j] = sum_m T[k][m] * K[m][j])
    float A2[9];
    #pragma unroll
    for (int k = 0; k < 3; k++)
        #pragma unroll
        for (int j = 0; j < 3; j++)
            A2[k * 3 + j] = fmaf(Tb[k * 4 + 0], K[0 * 3 + j],
                            fmaf(Tb[k * 4 + 1], K[1 * 3 + j],
                                 Tb[k * 4 + 2] * K[2 * 3 + j]));
    // M = Ki * A2
    #pragma unroll
    for (int r = 0; r < 3; r++)
        #pragma unroll
        for (int j = 0; j < 3; j++)
            g_M[bidx][r * 3 + j] = fmaf(Ki[r * 3 + 0], A2[0 * 3 + j],
                                   fmaf(Ki[r * 3 + 1], A2[1 * 3 + j],
                                        Ki[r * 3 + 2] * A2[2 * 3 + j]));
    // c = T[3,0:3] * K
    #pragma unroll
    for (int j = 0; j < 3; j++)
        g_M[bidx][9 + j] = fmaf(Tb[12], K[0 * 3 + j],
                           fmaf(Tb[13], K[1 * 3 + j],
                                Tb[14] * K[2 * 3 + j]));
}

// Pass 1: global max of uv over all pixels, folded per-batch affine chain.
__global__ void uv_max_kernel(const float* __restrict__ depth) {
    float local_max = -INFINITY;
    int stride = gridDim.x * blockDim.x;

    for (int g = blockIdx.x * blockDim.x + threadIdx.x; g < NGROUP; g += stride) {
        int hj4 = (g % (H_GRID / 4)) * 4;
        int t   = g / (H_GRID / 4);
        int wi  = t % W_GRID;
        int b   = t / W_GRID;

        float4 d4 = *reinterpret_cast<const float4*>(
            depth + ((size_t)b * W_GRID + wi) * H_GRID + hj4);
        const float* Mb = g_M[b];
        float u = (float)hj4, v = (float)wi;

        // e_j = u*M0j + v*M1j + M2j, incremental in u
        float e0 = fmaf(u, Mb[0], fmaf(v, Mb[3], Mb[6]));
        float e1 = fmaf(u, Mb[1], fmaf(v, Mb[4], Mb[7]));
        float e2 = fmaf(u, Mb[2], fmaf(v, Mb[5], Mb[8]));
        float c0 = Mb[9], c1 = Mb[10], c2 = Mb[11];

        float dv[4] = {d4.x, d4.y, d4.z, d4.w};
        #pragma unroll
        for (int k = 0; k < 4; k++) {
            float q0 = fmaf(dv[k], e0, c0);
            float q1 = fmaf(dv[k], e1, c1);
            float q2 = fmaf(dv[k], e2, c2);
            float rden = frcp_approx(q2 + 1e-4f);
            local_max = fmaxf(local_max, fmaxf(q0 * rden, q1 * rden));
            e0 += Mb[0]; e1 += Mb[1]; e2 += Mb[2];
        }
    }

    #pragma unroll
    for (int off = 16; off > 0; off >>= 1)
        local_max = fmaxf(local_max, __shfl_xor_sync(0xffffffffu, local_max, off));

    __shared__ float smax[8];
    int warp = threadIdx.x >> 5;
    int lane = threadIdx.x & 31;
    if (lane == 0) smax[warp] = local_max;
    __syncthreads();
    if (warp == 0) {
        float m = (lane < (blockDim.x >> 5)) ? smax[lane] : -INFINITY;
        #pragma unroll
        for (int off = 4; off > 0; off >>= 1)
            m = fmaxf(m, __shfl_xor_sync(0xffffffffu, m, off));
        if (lane == 0) atomicMax(&g_max_bits, float_to_ordered(m));
    }
}

// Pass 2: folded chain + bilinear sample. 4 px/thread, scalar gmax broadcast.
__global__ void __launch_bounds__(256, 5) sample_kernel(
    const float* __restrict__ depth,
    const float* __restrict__ image,
    float* __restrict__ out)
{
    int g = blockIdx.x * blockDim.x + threadIdx.x;
    if (g >= NGROUP) return;

    int hj4 = (g % (H_GRID / 4)) * 4;
    int t   = g / (H_GRID / 4);
    int wi  = t % W_GRID;
    int b   = t / W_GRID;

    float gmax = ordered_to_float(g_max_bits);
    float rg = __fdiv_rn(1.0f, gmax);
    float sx = (float)IMG_W * rg;
    float sy = (float)IMG_H * rg;

    float4 d4 = *reinterpret_cast<const float4*>(
        depth + ((size_t)b * W_GRID + wi) * H_GRID + hj4);
    const float* Mb = g_M[b];
    float u = (float)hj4, v = (float)wi;

    float e0 = fmaf(u, Mb[0], fmaf(v, Mb[3], Mb[6]));
    float e1 = fmaf(u, Mb[1], fmaf(v, Mb[4], Mb[7]));
    float e2 = fmaf(u, Mb[2], fmaf(v, Mb[5], Mb[8]));
    float c0 = Mb[9], c1 = Mb[10], c2 = Mb[11];
    float m0 = Mb[0], m1 = Mb[1], m2 = Mb[2];

    const float* img_b = image + (size_t)b * 3 * IMG_H * IMG_W;
    float r[3][4];
    float dv[4] = {d4.x, d4.y, d4.z, d4.w};

    #pragma unroll
    for (int k = 0; k < 4; k++) {
        float q0 = fmaf(dv[k], e0, c0);
        float q1 = fmaf(dv[k], e1, c1);
        float q2 = fmaf(dv[k], e2, c2);
        e0 += m0; e1 += m1; e2 += m2;

        float rden = frcp_approx(q2 + 1e-4f);
        float x = fmaf(q0, rden * sx, -0.5f);
        float y = fmaf(q1, rden * sy, -0.5f);

        float x0f = floorf(x);
        float y0f = floorf(y);
        float wx = x - x0f;
        float wy = y - y0f;
        float x1f = x0f + 1.0f;
        float y1f = y0f + 1.0f;

        float vx0 = (x0f >= 0.0f && x0f <= (float)(IMG_W - 1)) ? 1.0f : 0.0f;
        float vx1 = (x1f >= 0.0f && x1f <= (float)(IMG_W - 1)) ? 1.0f : 0.0f;
        float vy0 = (y0f >= 0.0f && y0f <= (float)(IMG_H - 1)) ? 1.0f : 0.0f;
        float vy1 = (y1f >= 0.0f && y1f <= (float)(IMG_H - 1)) ? 1.0f : 0.0f;

        int xi0 = (int)fminf(fmaxf(x0f, 0.0f), (float)(IMG_W - 1));
        int xi1 = (int)fminf(fmaxf(x1f, 0.0f), (float)(IMG_W - 1));
        int yi0 = (int)fminf(fmaxf(y0f, 0.0f), (float)(IMG_H - 1));
        int yi1 = (int)fminf(fmaxf(y1f, 0.0f), (float)(IMG_H - 1));

        float wx0 = 1.0f - wx, wy0 = 1.0f - wy;
        float w00 = wx0 * wy0 * (vx0 * vy0);
        float w01 = wx  * wy0 * (vx1 * vy0);
        float w10 = wx0 * wy  * (vx0 * vy1);
        float w11 = wx  * wy  * (vx1 * vy1);

        int dx  = xi1 - xi0;
        int i00 = yi0 * IMG_W + xi0;
        int i01 = i00 + dx;
        int i10 = i00 + (yi1 - yi0) * IMG_W;
        int i11 = i10 + dx;

        #pragma unroll
        for (int c = 0; c < 3; c++) {
            const float* ch = img_b + (size_t)c * (IMG_H * IMG_W);
            r[c][k] = w00 * ch[i00] + w01 * ch[i01] + w10 * ch[i10] + w11 * ch[i11];
        }
    }

    size_t out_base = ((size_t)b * 3) * (size_t)(W_GRID * H_GRID)
                    + (size_t)wi * H_GRID + hj4;
    #pragma unroll
    for (int c = 0; c < 3; c++) {
        float4 o = make_float4(r[c][0], r[c][1], r[c][2], r[c][3]);
        *reinterpret_cast<float4*>(out + out_base + (size_t)c * (W_GRID * H_GRID)) = o;
    }
}

extern "C" void kernel_launch(void* const* d_in, const int* in_sizes, int n_in,
                              void* d_out, int out_size) {
    const float* depth = (const float*)d_in[0];   // [32, 640, 480, 1]
    const float* T     = (const float*)d_in[1];   // [32, 4, 4]
    const float* image = (const float*)d_in[2];   // [32, 3, 480, 640]
    const float* K     = (const float*)d_in[3];   // [3, 3]
    float* out = (float*)d_out;                   // [32, 3, 640, 480]

    setup_kernel<<<1, 32>>>(T, K);
    uv_max_kernel<<<P1_BLOCKS, 256>>>(depth);
    int blocks = (NGROUP + 255) / 256;            // 9600
    sample_kernel<<<blocks, 256>>>(depth, image, out);
}